// round 4
// baseline (speedup 1.0000x reference)
#include <cuda_runtime.h>

// Problem constants
#define HW 4096            // 64*64
#define CIN 128
#define NOFF 18            // 2*K2
#define KD 1152            // CIN*9

// Scratch (device globals; no allocation allowed)
__device__ float g_h[8 * 128 * HW];        // BN+ReLU output, 16 MB
__device__ float g_off1[8 * NOFF * HW];    // conv_offsets
__device__ float g_off2[8 * NOFF * HW];    // dconv_offsets
__device__ float g_wt[KD * 128];           // dc_w transposed: [c*9+k2][oc]
__device__ float g_wtA[KD * NOFF];         // off_w transposed: [c*9+k2][oc<18]
__device__ float g_wtB[KD * NOFF];         // odc_w transposed

// ---------------------------------------------------------------------------
// K1: BN + ReLU (vectorized float4).
// ---------------------------------------------------------------------------
__global__ void k_bnrelu(const float* __restrict__ x,
                         const float* __restrict__ gamma,
                         const float* __restrict__ beta,
                         const float* __restrict__ mean,
                         const float* __restrict__ var) {
    int i = blockIdx.x * blockDim.x + threadIdx.x;   // float4 index
    int c = (i >> 10) & 127;                         // 1024 float4 per channel
    float s = rsqrtf(var[c] + 1e-5f) * gamma[c];
    float m = mean[c], bt = beta[c];
    float4 v = ((const float4*)x)[i];
    v.x = fmaxf((v.x - m) * s + bt, 0.f);
    v.y = fmaxf((v.y - m) * s + bt, 0.f);
    v.z = fmaxf((v.z - m) * s + bt, 0.f);
    v.w = fmaxf((v.w - m) * s + bt, 0.f);
    ((float4*)g_h)[i] = v;
}

// ---------------------------------------------------------------------------
// K0a: transpose dc_w [oc][c*9+k2] -> g_wt [c*9+k2][oc]. 147456 elements.
// ---------------------------------------------------------------------------
__global__ void k_transpose_w(const float* __restrict__ w) {
    int i = blockIdx.x * blockDim.x + threadIdx.x;
    int oc = i & 127, j = i >> 7;
    g_wt[i] = w[oc * KD + j];
}

// K0b: transpose an 18-oc weight [18][KD] -> dst [KD][18]. 20736 elements.
__global__ void k_transpose_w18(const float* __restrict__ w, float* __restrict__ dst) {
    int i = blockIdx.x * blockDim.x + threadIdx.x;
    if (i >= KD * NOFF) return;
    int j = i / NOFF, oc = i - j * NOFF;
    dst[i] = w[oc * KD + j];
}

// ---------------------------------------------------------------------------
// K2/K3 unified: (deformable) conv, 18 output channels, GEMM-tiled.
// Block: 32 pixels (half row) x 18 oc, 288 threads (9 warps).
// Grid: 512 rows * 2 halves = 1024 blocks.
// off == nullptr -> plain 3x3 conv (degenerate bilinear: one corner, weight 1).
// A-tile: sampled im2col [36][32] per 4-channel chunk; B-tile [36][18].
// ---------------------------------------------------------------------------
__global__ void __launch_bounds__(288) k_dconv_gemm18(
        const float* __restrict__ off,      // [b][18][HW] or nullptr
        const float* __restrict__ wt18,     // [KD][18] transposed weights
        const float* __restrict__ bias,     // [18]
        float* __restrict__ out) {          // [b][18][HW]
    __shared__ float s_w[4][288];    // bilinear weights [corner][k2*32+pix]
    __shared__ int   s_idx[4][288];  // clamped flat index y*64+x
    __shared__ float s_a[36][32];    // sampled A tile (j = c_local*9+k2)
    __shared__ float s_bw[36 * 18];  // weight B tile

    int tid = threadIdx.x;
    int blk = blockIdx.x;            // 1024 blocks
    int xh = blk & 1, row = blk >> 1;   // row in [0, 512)
    int b = row >> 6, y = row & 63, x0 = xh * 32;

    // Phase 0: bilinear setup for 32 pixels x 9 taps (288 pairs, 1/thread)
    {
        int t = tid;
        int pix = t & 31, k2 = t >> 5;
        int x = x0 + pix;
        float py, px;
        if (off) {
            const float* offp = off + b * NOFF * HW + y * 64 + x;
            py = (float)(y - 1 + k2 / 3) + offp[(2 * k2) * HW];
            px = (float)(x - 1 + k2 % 3) + offp[(2 * k2 + 1) * HW];
        } else {
            py = (float)(y - 1 + k2 / 3);
            px = (float)(x - 1 + k2 % 3);
        }
        float fy0 = floorf(py), fx0 = floorf(px);
        float wy1 = py - fy0, wx1 = px - fx0;
        float wy0 = 1.f - wy1, wx0 = 1.f - wx1;
        int iy0 = (int)fy0, ix0 = (int)fx0;
        int iy1 = iy0 + 1, ix1 = ix0 + 1;
        bool vy0 = ((unsigned)iy0 < 64u), vy1 = ((unsigned)iy1 < 64u);
        bool vx0 = ((unsigned)ix0 < 64u), vx1 = ((unsigned)ix1 < 64u);
        s_w[0][t] = (vy0 && vx0) ? wy0 * wx0 : 0.f;
        s_w[1][t] = (vy0 && vx1) ? wy0 * wx1 : 0.f;
        s_w[2][t] = (vy1 && vx0) ? wy1 * wx0 : 0.f;
        s_w[3][t] = (vy1 && vx1) ? wy1 * wx1 : 0.f;
        int cy0 = min(max(iy0, 0), 63), cy1 = min(max(iy1, 0), 63);
        int cx0 = min(max(ix0, 0), 63), cx1 = min(max(ix1, 0), 63);
        s_idx[0][t] = cy0 * 64 + cx0;
        s_idx[1][t] = cy0 * 64 + cx1;
        s_idx[2][t] = cy1 * 64 + cx0;
        s_idx[3][t] = cy1 * 64 + cx1;
    }

    int pix = tid & 31, ocp = tid >> 5;      // oc pair index 0..8
    float acc0 = bias[2 * ocp];
    float acc1 = bias[2 * ocp + 1];

    __syncthreads();

    const float* hb = g_h + (b << 7) * HW;

    for (int cc = 0; cc < 32; cc++) {        // 4-channel chunks
        // Fill A tile: 36 x 32 sampled values (4 per thread)
        for (int ii = tid; ii < 1152; ii += 288) {
            int p = ii & 31, j = ii >> 5;
            int cl = j / 9, k2 = j - cl * 9;
            int pt = k2 * 32 + p;
            const float* hp = hb + (cc * 4 + cl) * HW;
            float v = 0.f;
            float w0 = s_w[0][pt], w1 = s_w[1][pt];
            float w2 = s_w[2][pt], w3 = s_w[3][pt];
            if (w0 != 0.f) v  = w0 * hp[s_idx[0][pt]];
            if (w1 != 0.f) v += w1 * hp[s_idx[1][pt]];
            if (w2 != 0.f) v += w2 * hp[s_idx[2][pt]];
            if (w3 != 0.f) v += w3 * hp[s_idx[3][pt]];
            s_a[j][p] = v;
        }
        // Fill B tile: 36 x 18 weights (contiguous 648 floats)
        const float* wsrc = wt18 + cc * (36 * NOFF);
        for (int ii = tid; ii < 648; ii += 288)
            s_bw[ii] = wsrc[ii];
        __syncthreads();

#pragma unroll
        for (int j = 0; j < 36; j++) {
            float a = s_a[j][pix];
            float2 w = *(const float2*)&s_bw[j * NOFF + 2 * ocp];
            acc0 = fmaf(a, w.x, acc0);
            acc1 = fmaf(a, w.y, acc1);
        }
        __syncthreads();
    }

    int base = b * NOFF * HW + y * 64 + x0 + pix;
    out[base + (2 * ocp) * HW]     = acc0;
    out[base + (2 * ocp + 1) * HW] = acc1;
}

// ---------------------------------------------------------------------------
// K4: deformable conv, 128 output channels — GEMM-tiled.
// Block: 32 pixels (half row) x 128 oc, 256 threads, 4x4 register tile.
// ---------------------------------------------------------------------------
__global__ void __launch_bounds__(256) k_dconv128(
        const float* __restrict__ bias, float* __restrict__ out) {
    __shared__ float s_w[4][288];    // bilinear weights [corner][k2*32+pix]
    __shared__ int   s_idx[4][288];  // clamped flat index y*64+x
    __shared__ float s_a[36][32];    // sampled A tile (j = c_local*9+k2)
    __shared__ float s_b[36 * 128]; // weight B tile

    int tid = threadIdx.x;
    int blk = blockIdx.x;            // 1024 blocks
    int xh = blk & 1, row = blk >> 1;
    int b = row >> 6, y = row & 63, x0 = xh * 32;

    // Phase 0: bilinear setup for 32 pixels x 9 taps (288 pairs)
    for (int t = tid; t < 288; t += 256) {
        int pix = t & 31, k2 = t >> 5;
        int x = x0 + pix;
        const float* offp = g_off2 + b * NOFF * HW + y * 64 + x;
        float dy = offp[(2 * k2) * HW];
        float dx = offp[(2 * k2 + 1) * HW];
        float py = (float)(y - 1 + k2 / 3) + dy;
        float px = (float)(x - 1 + k2 % 3) + dx;
        float fy0 = floorf(py), fx0 = floorf(px);
        float wy1 = py - fy0, wx1 = px - fx0;
        float wy0 = 1.f - wy1, wx0 = 1.f - wx1;
        int iy0 = (int)fy0, ix0 = (int)fx0;
        int iy1 = iy0 + 1, ix1 = ix0 + 1;
        bool vy0 = ((unsigned)iy0 < 64u), vy1 = ((unsigned)iy1 < 64u);
        bool vx0 = ((unsigned)ix0 < 64u), vx1 = ((unsigned)ix1 < 64u);
        s_w[0][t] = (vy0 && vx0) ? wy0 * wx0 : 0.f;
        s_w[1][t] = (vy0 && vx1) ? wy0 * wx1 : 0.f;
        s_w[2][t] = (vy1 && vx0) ? wy1 * wx0 : 0.f;
        s_w[3][t] = (vy1 && vx1) ? wy1 * wx1 : 0.f;
        int cy0 = min(max(iy0, 0), 63), cy1 = min(max(iy1, 0), 63);
        int cx0 = min(max(ix0, 0), 63), cx1 = min(max(ix1, 0), 63);
        s_idx[0][t] = cy0 * 64 + cx0;
        s_idx[1][t] = cy0 * 64 + cx1;
        s_idx[2][t] = cy1 * 64 + cx0;
        s_idx[3][t] = cy1 * 64 + cx1;
    }

    float acc[4][4];
#pragma unroll
    for (int i = 0; i < 4; i++)
#pragma unroll
        for (int j = 0; j < 4; j++) acc[i][j] = 0.f;

    __syncthreads();

    const float* hb = g_h + (b << 7) * HW;
    int pq = tid & 7, oq = tid >> 3;     // pixel quad, oc quad

    for (int cc = 0; cc < 32; cc++) {    // 4-channel chunks
        // Fill A tile: 36 x 32 sampled values
        for (int ii = tid; ii < 1152; ii += 256) {
            int pix = ii & 31, j = ii >> 5;
            int cl = j / 9, k2 = j - cl * 9;
            int pt = k2 * 32 + pix;
            const float* hp = hb + (cc * 4 + cl) * HW;
            float v = s_w[0][pt] * hp[s_idx[0][pt]]
                    + s_w[1][pt] * hp[s_idx[1][pt]]
                    + s_w[2][pt] * hp[s_idx[2][pt]]
                    + s_w[3][pt] * hp[s_idx[3][pt]];
            s_a[j][pix] = v;
        }
        // Fill B tile: 36 x 128 weights (contiguous in g_wt)
        const float4* wsrc = (const float4*)g_wt + cc * 1152;
        for (int ii = tid; ii < 1152; ii += 256)
            ((float4*)s_b)[ii] = wsrc[ii];
        __syncthreads();

#pragma unroll
        for (int j = 0; j < 36; j++) {
            float4 a = *(const float4*)&s_a[j][pq * 4];
            float4 w = *(const float4*)&s_b[j * 128 + oq * 4];
            acc[0][0] += a.x * w.x; acc[0][1] += a.y * w.x;
            acc[0][2] += a.z * w.x; acc[0][3] += a.w * w.x;
            acc[1][0] += a.x * w.y; acc[1][1] += a.y * w.y;
            acc[1][2] += a.z * w.y; acc[1][3] += a.w * w.y;
            acc[2][0] += a.x * w.z; acc[2][1] += a.y * w.z;
            acc[2][2] += a.z * w.z; acc[2][3] += a.w * w.z;
            acc[3][0] += a.x * w.w; acc[3][1] += a.y * w.w;
            acc[3][2] += a.z * w.w; acc[3][3] += a.w * w.w;
        }
        __syncthreads();
    }

    // Epilogue: bias + float4 stores
#pragma unroll
    for (int oi = 0; oi < 4; oi++) {
        int oc = oq * 4 + oi;
        float bs = bias[oc];
        float4 r;
        r.x = acc[oi][0] + bs;
        r.y = acc[oi][1] + bs;
        r.z = acc[oi][2] + bs;
        r.w = acc[oi][3] + bs;
        *(float4*)&out[((b << 7) + oc) * HW + y * 64 + x0 + pq * 4] = r;
    }
}

// ---------------------------------------------------------------------------
// Launch. Input order: x, bn_gamma, bn_beta, bn_mean, bn_var,
// off_w, off_b, odc_w, odc_b, dc_w, dc_b. Output: float32 [8,128,64,64].
// ---------------------------------------------------------------------------
extern "C" void kernel_launch(void* const* d_in, const int* in_sizes, int n_in,
                              void* d_out, int out_size) {
    const float* x     = (const float*)d_in[0];
    const float* gamma = (const float*)d_in[1];
    const float* beta  = (const float*)d_in[2];
    const float* mean  = (const float*)d_in[3];
    const float* var   = (const float*)d_in[4];
    const float* off_w = (const float*)d_in[5];
    const float* off_b = (const float*)d_in[6];
    const float* odc_w = (const float*)d_in[7];
    const float* odc_b = (const float*)d_in[8];
    const float* dc_w  = (const float*)d_in[9];
    const float* dc_b  = (const float*)d_in[10];
    float* out = (float*)d_out;

    float *wtA, *wtB, *off1, *off2;
    cudaGetSymbolAddress((void**)&wtA,  g_wtA);
    cudaGetSymbolAddress((void**)&wtB,  g_wtB);
    cudaGetSymbolAddress((void**)&off1, g_off1);
    cudaGetSymbolAddress((void**)&off2, g_off2);

    k_bnrelu<<<4096, 256>>>(x, gamma, beta, mean, var);
    k_transpose_w<<<576, 256>>>(dc_w);
    k_transpose_w18<<<81, 256>>>(off_w, wtA);
    k_transpose_w18<<<81, 256>>>(odc_w, wtB);
    k_dconv_gemm18<<<1024, 288>>>(nullptr, wtA, off_b, off1);   // conv2d
    k_dconv_gemm18<<<1024, 288>>>(off1, wtB, odc_b, off2);      // deform 18ch
    k_dconv128<<<1024, 256>>>(dc_b, out);
}

// round 5
// speedup vs baseline: 1.3592x; 1.3592x over previous
#include <cuda_runtime.h>

// Problem constants
#define HW 4096            // 64*64
#define CIN 128
#define NOFF 18            // 2*K2
#define KD 1152            // CIN*9

// Scratch (device globals; no allocation allowed)
__device__ float g_h[8 * 128 * HW];        // BN+ReLU output, 16 MB
__device__ float g_off1[8 * NOFF * HW];    // conv_offsets
__device__ float g_off2[8 * NOFF * HW];    // dconv_offsets
__device__ float g_part[4 * 8 * NOFF * HW]; // 4 channel-chunk partials, 9.4 MB
__device__ float g_wt[KD * 128];           // dc_w transposed: [c*9+k2][oc]
__device__ float g_wtA[KD * NOFF];         // off_w transposed: [c*9+k2][oc<18]
__device__ float g_wtB[KD * NOFF];         // odc_w transposed

// ---------------------------------------------------------------------------
// K1: BN + ReLU (vectorized float4).
// ---------------------------------------------------------------------------
__global__ void k_bnrelu(const float* __restrict__ x,
                         const float* __restrict__ gamma,
                         const float* __restrict__ beta,
                         const float* __restrict__ mean,
                         const float* __restrict__ var) {
    int i = blockIdx.x * blockDim.x + threadIdx.x;   // float4 index
    int c = (i >> 10) & 127;                         // 1024 float4 per channel
    float s = rsqrtf(var[c] + 1e-5f) * gamma[c];
    float m = mean[c], bt = beta[c];
    float4 v = ((const float4*)x)[i];
    v.x = fmaxf((v.x - m) * s + bt, 0.f);
    v.y = fmaxf((v.y - m) * s + bt, 0.f);
    v.z = fmaxf((v.z - m) * s + bt, 0.f);
    v.w = fmaxf((v.w - m) * s + bt, 0.f);
    ((float4*)g_h)[i] = v;
}

// ---------------------------------------------------------------------------
// K0a: transpose dc_w [oc][c*9+k2] -> g_wt [c*9+k2][oc]. 147456 elements.
// ---------------------------------------------------------------------------
__global__ void k_transpose_w(const float* __restrict__ w) {
    int i = blockIdx.x * blockDim.x + threadIdx.x;
    int oc = i & 127, j = i >> 7;
    g_wt[i] = w[oc * KD + j];
}

// K0b: transpose an 18-oc weight [18][KD] -> dst [KD][18]. 20736 elements.
__global__ void k_transpose_w18(const float* __restrict__ w, float* __restrict__ dst) {
    int i = blockIdx.x * blockDim.x + threadIdx.x;
    if (i >= KD * NOFF) return;
    int j = i / NOFF, oc = i - j * NOFF;
    dst[i] = w[oc * KD + j];
}

// ---------------------------------------------------------------------------
// K2/K3: (deformable) conv, 18 output channels, channel-split partials.
// Block: 128 threads = 2 rows of 64 pixels; blockIdx.y = 32-channel chunk.
// Grid: (256, 4). Each thread keeps 18 register accumulators; writes its
// chunk partial to g_part[chunk]. off==nullptr -> plain 3x3 conv.
// Weights staged in smem as [cl][k2][18] (5184 floats = 20.7 KB).
// ---------------------------------------------------------------------------
__global__ void __launch_bounds__(128) k_dc18v2(
        const float* __restrict__ off,     // [b][18][HW] or nullptr
        const float* __restrict__ wtT) {   // [KD][18] transposed weights
    __shared__ float ws[32 * 9 * NOFF];    // 20736 B
    int tid = threadIdx.x;
    int row = blockIdx.x * 2 + (tid >> 6);    // b*64+y
    int b = row >> 6, y = row & 63, x = tid & 63;
    int chunk = blockIdx.y;                    // 0..3
    int c0 = chunk * 32;

    // Stage this chunk's weights: rows c0*9 .. c0*9+287 of wtT, 5184 floats
    const float* wsrc = wtT + c0 * 9 * NOFF;
    for (int i = tid; i < 32 * 9 * NOFF; i += 128) ws[i] = wsrc[i];
    __syncthreads();

    float acc[NOFF];
#pragma unroll
    for (int o = 0; o < NOFF; o++) acc[o] = 0.f;

    const float* hb = g_h + ((b << 7) + c0) * HW;

    if (off) {
        const float* offp = off + b * NOFF * HW + y * 64 + x;
        for (int k2 = 0; k2 < 9; k2++) {
            float py = (float)(y - 1 + k2 / 3) + offp[(2 * k2) * HW];
            float px = (float)(x - 1 + k2 % 3) + offp[(2 * k2 + 1) * HW];
            float fy0 = floorf(py), fx0 = floorf(px);
            float wy1 = py - fy0, wx1 = px - fx0;
            float wy0 = 1.f - wy1, wx0 = 1.f - wx1;
            int iy0 = (int)fy0, ix0 = (int)fx0;
            int iy1 = iy0 + 1, ix1 = ix0 + 1;
            bool vy0 = ((unsigned)iy0 < 64u), vy1 = ((unsigned)iy1 < 64u);
            bool vx0 = ((unsigned)ix0 < 64u), vx1 = ((unsigned)ix1 < 64u);
            float w00 = (vy0 && vx0) ? wy0 * wx0 : 0.f;
            float w01 = (vy0 && vx1) ? wy0 * wx1 : 0.f;
            float w10 = (vy1 && vx0) ? wy1 * wx0 : 0.f;
            float w11 = (vy1 && vx1) ? wy1 * wx1 : 0.f;
            int cy0 = min(max(iy0, 0), 63), cy1 = min(max(iy1, 0), 63);
            int cx0 = min(max(ix0, 0), 63), cx1 = min(max(ix1, 0), 63);
            int i00 = cy0 * 64 + cx0, i01 = cy0 * 64 + cx1;
            int i10 = cy1 * 64 + cx0, i11 = cy1 * 64 + cx1;

            const float* hp = hb;
            for (int cl = 0; cl < 32; cl++, hp += HW) {
                float s = w00 * hp[i00] + w01 * hp[i01]
                        + w10 * hp[i10] + w11 * hp[i11];
                const float* wr = ws + (cl * 9 + k2) * NOFF;
#pragma unroll
                for (int op = 0; op < 9; op++) {
                    float2 w = *(const float2*)&wr[2 * op];
                    acc[2 * op]     = fmaf(s, w.x, acc[2 * op]);
                    acc[2 * op + 1] = fmaf(s, w.y, acc[2 * op + 1]);
                }
            }
        }
    } else {
        for (int k2 = 0; k2 < 9; k2++) {
            int yy = y - 1 + k2 / 3, xx = x - 1 + k2 % 3;
            bool v = ((unsigned)yy < 64u) && ((unsigned)xx < 64u);
            int idx = v ? (yy * 64 + xx) : 0;
            const float* hp = hb;
            for (int cl = 0; cl < 32; cl++, hp += HW) {
                float s = v ? hp[idx] : 0.f;
                const float* wr = ws + (cl * 9 + k2) * NOFF;
#pragma unroll
                for (int op = 0; op < 9; op++) {
                    float2 w = *(const float2*)&wr[2 * op];
                    acc[2 * op]     = fmaf(s, w.x, acc[2 * op]);
                    acc[2 * op + 1] = fmaf(s, w.y, acc[2 * op + 1]);
                }
            }
        }
    }

    float* dst = g_part + chunk * (8 * NOFF * HW) + b * NOFF * HW + y * 64 + x;
#pragma unroll
    for (int o = 0; o < NOFF; o++) dst[o * HW] = acc[o];
}

// ---------------------------------------------------------------------------
// Reduce 4 chunk partials + bias -> dst. 147456 float4.
// ---------------------------------------------------------------------------
__global__ void k_reduce18(const float* __restrict__ bias,
                           float* __restrict__ dst) {
    int i = blockIdx.x * blockDim.x + threadIdx.x;   // float4 index
    int o = (i >> 10) % NOFF;                        // 1024 float4 per channel
    float bs = bias[o];
    const float4* p = (const float4*)g_part;
    float4 a = p[i];
    float4 b4 = p[i + 147456];
    float4 c4 = p[i + 2 * 147456];
    float4 d4 = p[i + 3 * 147456];
    float4 r;
    r.x = a.x + b4.x + c4.x + d4.x + bs;
    r.y = a.y + b4.y + c4.y + d4.y + bs;
    r.z = a.z + b4.z + c4.z + d4.z + bs;
    r.w = a.w + b4.w + c4.w + d4.w + bs;
    ((float4*)dst)[i] = r;
}

// ---------------------------------------------------------------------------
// K4: deformable conv, 128 output channels — GEMM-tiled (unchanged).
// ---------------------------------------------------------------------------
__global__ void __launch_bounds__(256) k_dconv128(
        const float* __restrict__ bias, float* __restrict__ out) {
    __shared__ float s_w[4][288];    // bilinear weights [corner][k2*32+pix]
    __shared__ int   s_idx[4][288];  // clamped flat index y*64+x
    __shared__ float s_a[36][32];    // sampled A tile (j = c_local*9+k2)
    __shared__ float s_b[36 * 128];  // weight B tile

    int tid = threadIdx.x;
    int blk = blockIdx.x;            // 1024 blocks
    int xh = blk & 1, row = blk >> 1;
    int b = row >> 6, y = row & 63, x0 = xh * 32;

    for (int t = tid; t < 288; t += 256) {
        int pix = t & 31, k2 = t >> 5;
        int x = x0 + pix;
        const float* offp = g_off2 + b * NOFF * HW + y * 64 + x;
        float dy = offp[(2 * k2) * HW];
        float dx = offp[(2 * k2 + 1) * HW];
        float py = (float)(y - 1 + k2 / 3) + dy;
        float px = (float)(x - 1 + k2 % 3) + dx;
        float fy0 = floorf(py), fx0 = floorf(px);
        float wy1 = py - fy0, wx1 = px - fx0;
        float wy0 = 1.f - wy1, wx0 = 1.f - wx1;
        int iy0 = (int)fy0, ix0 = (int)fx0;
        int iy1 = iy0 + 1, ix1 = ix0 + 1;
        bool vy0 = ((unsigned)iy0 < 64u), vy1 = ((unsigned)iy1 < 64u);
        bool vx0 = ((unsigned)ix0 < 64u), vx1 = ((unsigned)ix1 < 64u);
        s_w[0][t] = (vy0 && vx0) ? wy0 * wx0 : 0.f;
        s_w[1][t] = (vy0 && vx1) ? wy0 * wx1 : 0.f;
        s_w[2][t] = (vy1 && vx0) ? wy1 * wx0 : 0.f;
        s_w[3][t] = (vy1 && vx1) ? wy1 * wx1 : 0.f;
        int cy0 = min(max(iy0, 0), 63), cy1 = min(max(iy1, 0), 63);
        int cx0 = min(max(ix0, 0), 63), cx1 = min(max(ix1, 0), 63);
        s_idx[0][t] = cy0 * 64 + cx0;
        s_idx[1][t] = cy0 * 64 + cx1;
        s_idx[2][t] = cy1 * 64 + cx0;
        s_idx[3][t] = cy1 * 64 + cx1;
    }

    float acc[4][4];
#pragma unroll
    for (int i = 0; i < 4; i++)
#pragma unroll
        for (int j = 0; j < 4; j++) acc[i][j] = 0.f;

    __syncthreads();

    const float* hb = g_h + (b << 7) * HW;
    int pq = tid & 7, oq = tid >> 3;     // pixel quad, oc quad

    for (int cc = 0; cc < 32; cc++) {    // 4-channel chunks
        for (int ii = tid; ii < 1152; ii += 256) {
            int pix = ii & 31, j = ii >> 5;
            int cl = j / 9, k2 = j - cl * 9;
            int pt = k2 * 32 + pix;
            const float* hp = hb + (cc * 4 + cl) * HW;
            float v = s_w[0][pt] * hp[s_idx[0][pt]]
                    + s_w[1][pt] * hp[s_idx[1][pt]]
                    + s_w[2][pt] * hp[s_idx[2][pt]]
                    + s_w[3][pt] * hp[s_idx[3][pt]];
            s_a[j][pix] = v;
        }
        const float4* wsrc = (const float4*)g_wt + cc * 1152;
        for (int ii = tid; ii < 1152; ii += 256)
            ((float4*)s_b)[ii] = wsrc[ii];
        __syncthreads();

#pragma unroll
        for (int j = 0; j < 36; j++) {
            float4 a = *(const float4*)&s_a[j][pq * 4];
            float4 w = *(const float4*)&s_b[j * 128 + oq * 4];
            acc[0][0] += a.x * w.x; acc[0][1] += a.y * w.x;
            acc[0][2] += a.z * w.x; acc[0][3] += a.w * w.x;
            acc[1][0] += a.x * w.y; acc[1][1] += a.y * w.y;
            acc[1][2] += a.z * w.y; acc[1][3] += a.w * w.y;
            acc[2][0] += a.x * w.z; acc[2][1] += a.y * w.z;
            acc[2][2] += a.z * w.z; acc[2][3] += a.w * w.z;
            acc[3][0] += a.x * w.w; acc[3][1] += a.y * w.w;
            acc[3][2] += a.z * w.w; acc[3][3] += a.w * w.w;
        }
        __syncthreads();
    }

#pragma unroll
    for (int oi = 0; oi < 4; oi++) {
        int oc = oq * 4 + oi;
        float bs = bias[oc];
        float4 r;
        r.x = acc[oi][0] + bs;
        r.y = acc[oi][1] + bs;
        r.z = acc[oi][2] + bs;
        r.w = acc[oi][3] + bs;
        *(float4*)&out[((b << 7) + oc) * HW + y * 64 + x0 + pq * 4] = r;
    }
}

// ---------------------------------------------------------------------------
// Launch. Input order: x, bn_gamma, bn_beta, bn_mean, bn_var,
// off_w, off_b, odc_w, odc_b, dc_w, dc_b. Output: float32 [8,128,64,64].
// ---------------------------------------------------------------------------
extern "C" void kernel_launch(void* const* d_in, const int* in_sizes, int n_in,
                              void* d_out, int out_size) {
    const float* x     = (const float*)d_in[0];
    const float* gamma = (const float*)d_in[1];
    const float* beta  = (const float*)d_in[2];
    const float* mean  = (const float*)d_in[3];
    const float* var   = (const float*)d_in[4];
    const float* off_w = (const float*)d_in[5];
    const float* off_b = (const float*)d_in[6];
    const float* odc_w = (const float*)d_in[7];
    const float* odc_b = (const float*)d_in[8];
    const float* dc_w  = (const float*)d_in[9];
    const float* dc_b  = (const float*)d_in[10];
    float* out = (float*)d_out;

    float *wtA, *wtB, *off1, *off2;
    cudaGetSymbolAddress((void**)&wtA,  g_wtA);
    cudaGetSymbolAddress((void**)&wtB,  g_wtB);
    cudaGetSymbolAddress((void**)&off1, g_off1);
    cudaGetSymbolAddress((void**)&off2, g_off2);

    k_bnrelu<<<4096, 256>>>(x, gamma, beta, mean, var);
    k_transpose_w<<<576, 256>>>(dc_w);
    k_transpose_w18<<<81, 256>>>(off_w, wtA);
    k_transpose_w18<<<81, 256>>>(odc_w, wtB);
    k_dc18v2<<<dim3(256, 4), 128>>>(nullptr, wtA);      // conv2d partials
    k_reduce18<<<576, 256>>>(off_b, off1);
    k_dc18v2<<<dim3(256, 4), 128>>>(off1, wtB);         // deform18 partials
    k_reduce18<<<576, 256>>>(odc_b, off2);
    k_dconv128<<<1024, 256>>>(dc_b, out);
}

// round 6
// speedup vs baseline: 2.0421x; 1.5024x over previous
#include <cuda_runtime.h>

// Problem constants
#define HW 4096            // 64*64
#define CIN 128
#define NOFF 18            // 2*K2
#define KD 1152            // CIN*9

// Scratch (device globals; no allocation allowed)
__device__ float g_h[8 * 128 * HW];        // BN+ReLU output, 16 MB
__device__ float g_off1[8 * NOFF * HW];    // conv_offsets
__device__ float g_off2[8 * NOFF * HW];    // dconv_offsets
__device__ float g_part[4 * 8 * NOFF * HW]; // 4 channel-chunk partials
__device__ unsigned g_wt2[KD * 128];       // dc_w tap-major tf32: [k2*128+c][oc]
__device__ float g_wtA[KD * NOFF];         // off_w transposed: [c*9+k2][oc<18]
__device__ float g_wtB[KD * NOFF];         // odc_w transposed

// ---------------------------------------------------------------------------
// K1: BN + ReLU (vectorized float4).
// ---------------------------------------------------------------------------
__global__ void k_bnrelu(const float* __restrict__ x,
                         const float* __restrict__ gamma,
                         const float* __restrict__ beta,
                         const float* __restrict__ mean,
                         const float* __restrict__ var) {
    int i = blockIdx.x * blockDim.x + threadIdx.x;
    int c = (i >> 10) & 127;
    float s = rsqrtf(var[c] + 1e-5f) * gamma[c];
    float m = mean[c], bt = beta[c];
    float4 v = ((const float4*)x)[i];
    v.x = fmaxf((v.x - m) * s + bt, 0.f);
    v.y = fmaxf((v.y - m) * s + bt, 0.f);
    v.z = fmaxf((v.z - m) * s + bt, 0.f);
    v.w = fmaxf((v.w - m) * s + bt, 0.f);
    ((float4*)g_h)[i] = v;
}

// ---------------------------------------------------------------------------
// K0a: dc_w [oc][c*9+k2] -> g_wt2 tap-major tf32 [k2*128+c][oc].
// ---------------------------------------------------------------------------
__global__ void k_transpose_wt(const float* __restrict__ w) {
    int i = blockIdx.x * blockDim.x + threadIdx.x;   // 147456
    int oc = i & 127, jp = i >> 7;
    int k2 = jp >> 7, c = jp & 127;
    float v = w[oc * KD + c * 9 + k2];
    unsigned t;
    asm("cvt.rna.tf32.f32 %0, %1;" : "=r"(t) : "f"(v));
    g_wt2[i] = t;
}

// K0b: transpose an 18-oc weight [18][KD] -> dst [KD][18].
__global__ void k_transpose_w18(const float* __restrict__ w, float* __restrict__ dst) {
    int i = blockIdx.x * blockDim.x + threadIdx.x;
    if (i >= KD * NOFF) return;
    int j = i / NOFF, oc = i - j * NOFF;
    dst[i] = w[oc * KD + j];
}

// ---------------------------------------------------------------------------
// K2/K3: (deformable) conv, 18 oc, channel-split partials (unchanged R5).
// ---------------------------------------------------------------------------
__global__ void __launch_bounds__(128) k_dc18v2(
        const float* __restrict__ off,
        const float* __restrict__ wtT) {
    __shared__ float ws[32 * 9 * NOFF];
    int tid = threadIdx.x;
    int row = blockIdx.x * 2 + (tid >> 6);
    int b = row >> 6, y = row & 63, x = tid & 63;
    int chunk = blockIdx.y;
    int c0 = chunk * 32;

    const float* wsrc = wtT + c0 * 9 * NOFF;
    for (int i = tid; i < 32 * 9 * NOFF; i += 128) ws[i] = wsrc[i];
    __syncthreads();

    float acc[NOFF];
#pragma unroll
    for (int o = 0; o < NOFF; o++) acc[o] = 0.f;

    const float* hb = g_h + ((b << 7) + c0) * HW;

    if (off) {
        const float* offp = off + b * NOFF * HW + y * 64 + x;
        for (int k2 = 0; k2 < 9; k2++) {
            float py = (float)(y - 1 + k2 / 3) + offp[(2 * k2) * HW];
            float px = (float)(x - 1 + k2 % 3) + offp[(2 * k2 + 1) * HW];
            float fy0 = floorf(py), fx0 = floorf(px);
            float wy1 = py - fy0, wx1 = px - fx0;
            float wy0 = 1.f - wy1, wx0 = 1.f - wx1;
            int iy0 = (int)fy0, ix0 = (int)fx0;
            int iy1 = iy0 + 1, ix1 = ix0 + 1;
            bool vy0 = ((unsigned)iy0 < 64u), vy1 = ((unsigned)iy1 < 64u);
            bool vx0 = ((unsigned)ix0 < 64u), vx1 = ((unsigned)ix1 < 64u);
            float w00 = (vy0 && vx0) ? wy0 * wx0 : 0.f;
            float w01 = (vy0 && vx1) ? wy0 * wx1 : 0.f;
            float w10 = (vy1 && vx0) ? wy1 * wx0 : 0.f;
            float w11 = (vy1 && vx1) ? wy1 * wx1 : 0.f;
            int cy0 = min(max(iy0, 0), 63), cy1 = min(max(iy1, 0), 63);
            int cx0 = min(max(ix0, 0), 63), cx1 = min(max(ix1, 0), 63);
            int i00 = cy0 * 64 + cx0, i01 = cy0 * 64 + cx1;
            int i10 = cy1 * 64 + cx0, i11 = cy1 * 64 + cx1;

            const float* hp = hb;
            for (int cl = 0; cl < 32; cl++, hp += HW) {
                float s = w00 * hp[i00] + w01 * hp[i01]
                        + w10 * hp[i10] + w11 * hp[i11];
                const float* wr = ws + (cl * 9 + k2) * NOFF;
#pragma unroll
                for (int op = 0; op < 9; op++) {
                    float2 w = *(const float2*)&wr[2 * op];
                    acc[2 * op]     = fmaf(s, w.x, acc[2 * op]);
                    acc[2 * op + 1] = fmaf(s, w.y, acc[2 * op + 1]);
                }
            }
        }
    } else {
        for (int k2 = 0; k2 < 9; k2++) {
            int yy = y - 1 + k2 / 3, xx = x - 1 + k2 % 3;
            bool v = ((unsigned)yy < 64u) && ((unsigned)xx < 64u);
            int idx = v ? (yy * 64 + xx) : 0;
            const float* hp = hb;
            for (int cl = 0; cl < 32; cl++, hp += HW) {
                float s = v ? hp[idx] : 0.f;
                const float* wr = ws + (cl * 9 + k2) * NOFF;
#pragma unroll
                for (int op = 0; op < 9; op++) {
                    float2 w = *(const float2*)&wr[2 * op];
                    acc[2 * op]     = fmaf(s, w.x, acc[2 * op]);
                    acc[2 * op + 1] = fmaf(s, w.y, acc[2 * op + 1]);
                }
            }
        }
    }

    float* dst = g_part + chunk * (8 * NOFF * HW) + b * NOFF * HW + y * 64 + x;
#pragma unroll
    for (int o = 0; o < NOFF; o++) dst[o * HW] = acc[o];
}

// ---------------------------------------------------------------------------
// Reduce 4 chunk partials + bias -> dst.
// ---------------------------------------------------------------------------
__global__ void k_reduce18(const float* __restrict__ bias,
                           float* __restrict__ dst) {
    int i = blockIdx.x * blockDim.x + threadIdx.x;
    int o = (i >> 10) % NOFF;
    float bs = bias[o];
    const float4* p = (const float4*)g_part;
    float4 a = p[i];
    float4 b4 = p[i + 147456];
    float4 c4 = p[i + 2 * 147456];
    float4 d4 = p[i + 3 * 147456];
    float4 r;
    r.x = a.x + b4.x + c4.x + d4.x + bs;
    r.y = a.y + b4.y + c4.y + d4.y + bs;
    r.z = a.z + b4.z + c4.z + d4.z + bs;
    r.w = a.w + b4.w + c4.w + d4.w + bs;
    ((float4*)dst)[i] = r;
}

// ---------------------------------------------------------------------------
// K4: deformable conv, 128 oc — tf32 mma.sync GEMM.
// Block = one image row: 64 px x 128 oc. 512 blocks, 256 threads (8 warps).
// Warp tile 32px x 32oc = 2 m-tiles x 4 n-tiles of m16n8k8.
// K order tap-major (j' = k2*128 + c); chunk = 32 K (one tap, 32 channels).
// ---------------------------------------------------------------------------
__device__ __forceinline__ void mma_tf32(float* d, const unsigned* a,
                                         unsigned b0, unsigned b1) {
    asm volatile(
        "mma.sync.aligned.m16n8k8.row.col.f32.tf32.tf32.f32 "
        "{%0,%1,%2,%3}, {%4,%5,%6,%7}, {%8,%9}, {%0,%1,%2,%3};"
        : "+f"(d[0]), "+f"(d[1]), "+f"(d[2]), "+f"(d[3])
        : "r"(a[0]), "r"(a[1]), "r"(a[2]), "r"(a[3]), "r"(b0), "r"(b1));
}

__global__ void __launch_bounds__(256, 2) k_dconv128_mma(
        const float* __restrict__ bias, float* __restrict__ out) {
    __shared__ float4   s_wq[576];        // bilinear weights [k2*64+px]
    __shared__ int4     s_iq[576];        // corner indices
    __shared__ unsigned s_a[32][72];      // tf32 A tile [k][px], pad 72
    __shared__ unsigned s_b[32][136];     // tf32 B tile [k][oc], pad 136

    int tid = threadIdx.x;
    int row = blockIdx.x;                 // b*64 + y
    int b = row >> 6, y = row & 63;

    // Phase 0: bilinear setup for 64 px x 9 taps
    for (int t = tid; t < 576; t += 256) {
        int px = t & 63, k2 = t >> 6;
        const float* offp = g_off2 + b * NOFF * HW + y * 64 + px;
        float py = (float)(y - 1 + k2 / 3) + offp[(2 * k2) * HW];
        float pxf = (float)(px - 1 + k2 % 3) + offp[(2 * k2 + 1) * HW];
        float fy0 = floorf(py), fx0 = floorf(pxf);
        float wy1 = py - fy0, wx1 = pxf - fx0;
        float wy0 = 1.f - wy1, wx0 = 1.f - wx1;
        int iy0 = (int)fy0, ix0 = (int)fx0;
        int iy1 = iy0 + 1, ix1 = ix0 + 1;
        bool vy0 = ((unsigned)iy0 < 64u), vy1 = ((unsigned)iy1 < 64u);
        bool vx0 = ((unsigned)ix0 < 64u), vx1 = ((unsigned)ix1 < 64u);
        float4 w;
        w.x = (vy0 && vx0) ? wy0 * wx0 : 0.f;
        w.y = (vy0 && vx1) ? wy0 * wx1 : 0.f;
        w.z = (vy1 && vx0) ? wy1 * wx0 : 0.f;
        w.w = (vy1 && vx1) ? wy1 * wx1 : 0.f;
        int cy0 = min(max(iy0, 0), 63), cy1 = min(max(iy1, 0), 63);
        int cx0 = min(max(ix0, 0), 63), cx1 = min(max(ix1, 0), 63);
        s_wq[t] = w;
        s_iq[t] = make_int4(cy0 * 64 + cx0, cy0 * 64 + cx1,
                            cy1 * 64 + cx0, cy1 * 64 + cx1);
    }
    __syncthreads();

    int lane = tid & 31, warp = tid >> 5;
    int pxw = (warp & 1) * 32;            // warp px base
    int ocw = (warp >> 1) * 32;           // warp oc base
    int gid = lane >> 2, tig = lane & 3;

    float acc[2][4][4];
#pragma unroll
    for (int mt = 0; mt < 2; mt++)
#pragma unroll
        for (int nt = 0; nt < 4; nt++)
#pragma unroll
            for (int q = 0; q < 4; q++) acc[mt][nt][q] = 0.f;

    int px_s = tid & 63, cl0 = (tid >> 6) * 8;   // sampling assignment
    const float* hb = g_h + (b << 7) * HW;

    for (int kc = 0; kc < 36; kc++) {
        int k2 = kc >> 2, c0 = (kc & 3) * 32;

        // Stage B tile: rows kc*32..+32 of g_wt2 (32x128 tf32)
        const uint4* wsrc = (const uint4*)g_wt2 + kc * 1024;
        for (int i = tid; i < 1024; i += 256) {
            uint4 v = wsrc[i];
            int r = i >> 5, c4 = (i & 31) * 4;
            *(uint4*)&s_b[r][c4] = v;
        }

        // Sample A tile: 64 px x 32 channels (8 values/thread, w/idx in regs)
        {
            float4 w = s_wq[k2 * 64 + px_s];
            int4  ix = s_iq[k2 * 64 + px_s];
            const float* hp = hb + (c0 + cl0) * HW;
#pragma unroll
            for (int i = 0; i < 8; i++, hp += HW) {
                float v = w.x * hp[ix.x] + w.y * hp[ix.y]
                        + w.z * hp[ix.z] + w.w * hp[ix.w];
                unsigned t32;
                asm("cvt.rna.tf32.f32 %0, %1;" : "=r"(t32) : "f"(v));
                s_a[cl0 + i][px_s] = t32;
            }
        }
        __syncthreads();

        // MMA phase: 4 k8-steps x (2 m-tiles x 4 n-tiles)
#pragma unroll
        for (int k0 = 0; k0 < 32; k0 += 8) {
            unsigned a[2][4];
#pragma unroll
            for (int mt = 0; mt < 2; mt++) {
                int pxb = pxw + mt * 16;
                a[mt][0] = s_a[k0 + tig][pxb + gid];
                a[mt][1] = s_a[k0 + tig][pxb + gid + 8];
                a[mt][2] = s_a[k0 + tig + 4][pxb + gid];
                a[mt][3] = s_a[k0 + tig + 4][pxb + gid + 8];
            }
#pragma unroll
            for (int nt = 0; nt < 4; nt++) {
                unsigned b0 = s_b[k0 + tig][ocw + nt * 8 + gid];
                unsigned b1 = s_b[k0 + tig + 4][ocw + nt * 8 + gid];
                mma_tf32(acc[0][nt], a[0], b0, b1);
                mma_tf32(acc[1][nt], a[1], b0, b1);
            }
        }
        __syncthreads();
    }

    // Epilogue: bias + scalar stores per fragment element
    int obase = (b << 7) * HW + y * 64;
#pragma unroll
    for (int nt = 0; nt < 4; nt++) {
        int oc0 = ocw + nt * 8 + 2 * tig;
        float bs0 = bias[oc0], bs1 = bias[oc0 + 1];
#pragma unroll
        for (int mt = 0; mt < 2; mt++) {
            int px0 = pxw + mt * 16 + gid;
            out[obase + oc0 * HW + px0]           = acc[mt][nt][0] + bs0;
            out[obase + (oc0 + 1) * HW + px0]     = acc[mt][nt][1] + bs1;
            out[obase + oc0 * HW + px0 + 8]       = acc[mt][nt][2] + bs0;
            out[obase + (oc0 + 1) * HW + px0 + 8] = acc[mt][nt][3] + bs1;
        }
    }
}

// ---------------------------------------------------------------------------
// Launch. Input order: x, bn_gamma, bn_beta, bn_mean, bn_var,
// off_w, off_b, odc_w, odc_b, dc_w, dc_b. Output: float32 [8,128,64,64].
// ---------------------------------------------------------------------------
extern "C" void kernel_launch(void* const* d_in, const int* in_sizes, int n_in,
                              void* d_out, int out_size) {
    const float* x     = (const float*)d_in[0];
    const float* gamma = (const float*)d_in[1];
    const float* beta  = (const float*)d_in[2];
    const float* mean  = (const float*)d_in[3];
    const float* var   = (const float*)d_in[4];
    const float* off_w = (const float*)d_in[5];
    const float* off_b = (const float*)d_in[6];
    const float* odc_w = (const float*)d_in[7];
    const float* odc_b = (const float*)d_in[8];
    const float* dc_w  = (const float*)d_in[9];
    const float* dc_b  = (const float*)d_in[10];
    float* out = (float*)d_out;

    float *wtA, *wtB, *off1, *off2;
    cudaGetSymbolAddress((void**)&wtA,  g_wtA);
    cudaGetSymbolAddress((void**)&wtB,  g_wtB);
    cudaGetSymbolAddress((void**)&off1, g_off1);
    cudaGetSymbolAddress((void**)&off2, g_off2);

    k_bnrelu<<<4096, 256>>>(x, gamma, beta, mean, var);
    k_transpose_wt<<<576, 256>>>(dc_w);
    k_transpose_w18<<<81, 256>>>(off_w, wtA);
    k_transpose_w18<<<81, 256>>>(odc_w, wtB);
    k_dc18v2<<<dim3(256, 4), 128>>>(nullptr, wtA);      // conv2d partials
    k_reduce18<<<576, 256>>>(off_b, off1);
    k_dc18v2<<<dim3(256, 4), 128>>>(off1, wtB);         // deform18 partials
    k_reduce18<<<576, 256>>>(odc_b, off2);
    k_dconv128_mma<<<512, 256>>>(dc_b, out);
}